// round 12
// baseline (speedup 1.0000x reference)
#include <cuda_runtime.h>
#include <cuda_bf16.h>
#include <cuda_fp8.h>
#include <math.h>
#include <stdint.h>

#define BATCH 128
#define NOSC  1024
#define STEPS 10
#define DT    0.1f
#define BN    (BATCH*NOSC)

#define TM 32
#define TN 32
#define NCHUNK 8              // k-chunks of 128 fp8 (=128B row, same swizzle)
#define QCH 2                 // chunks per quarter
#define TILE_B 4096           // 32 rows x 128B, XOR-swizzled
#define CHUNK_B (3*TILE_B)
#define SMEM_BYTES (NCHUNK*CHUNK_B)   // 98304 B

// ---------------- persistent device state (no allocation allowed) -------------
__device__ float    g_theta[BN];
__device__ float    g_sf[BN];          // fp32 sin, owner-thread read/write only
__device__ float    g_cf[BN];          // fp32 cos, owner-thread read/write only
__device__ uint8_t  g_s8[2][BN];       // e4m3 sin, double-buffered (GEMM input)
__device__ uint8_t  g_c8[2][BN];       // e4m3 cos
__device__ uint8_t  g_K8[NOSC*NOSC];   // e4m3 K

// ---------------- helpers -----------------------------------------------------
__device__ __forceinline__ uint32_t s2u(const void* p) {
    return (uint32_t)__cvta_generic_to_shared(p);
}
__device__ __forceinline__ void cp16(uint32_t dst, const void* src) {
    asm volatile("cp.async.cg.shared.global [%0], [%1], 16;"
                 :: "r"(dst), "l"(src) : "memory");
}
__device__ __forceinline__ void ldsm4(uint32_t& r0, uint32_t& r1, uint32_t& r2,
                                      uint32_t& r3, uint32_t a) {
    asm volatile("ldmatrix.sync.aligned.m8n8.x4.shared.b16 {%0,%1,%2,%3}, [%4];"
                 : "=r"(r0), "=r"(r1), "=r"(r2), "=r"(r3) : "r"(a));
}
__device__ __forceinline__ void mma_fp8(float* d, const uint32_t* a,
                                        uint32_t b0, uint32_t b1) {
    asm volatile(
        "mma.sync.aligned.m16n8k32.row.col.f32.e4m3.e4m3.f32 "
        "{%0,%1,%2,%3}, {%4,%5,%6,%7}, {%8,%9}, {%0,%1,%2,%3};"
        : "+f"(d[0]), "+f"(d[1]), "+f"(d[2]), "+f"(d[3])
        : "r"(a[0]), "r"(a[1]), "r"(a[2]), "r"(a[3]), "r"(b0), "r"(b1));
}
__device__ __forceinline__ uint8_t f2e4m3(float x) {
    return (uint8_t)__nv_cvt_float_to_fp8(x, __NV_SATFINITE, __NV_E4M3);
}

// ---------------- init: fp8 K + fp8/fp32 sin,cos + theta ----------------------
__global__ void init_kernel(const float* __restrict__ theta_init,
                            const float* __restrict__ K) {
    int i4 = (blockIdx.x * blockDim.x + threadIdx.x) * 4;
    float4 k4 = *reinterpret_cast<const float4*>(&K[i4]);
    uint32_t kp = (uint32_t)f2e4m3(k4.x) | ((uint32_t)f2e4m3(k4.y) << 8)
                | ((uint32_t)f2e4m3(k4.z) << 16) | ((uint32_t)f2e4m3(k4.w) << 24);
    *reinterpret_cast<uint32_t*>(&g_K8[i4]) = kp;
    if (i4 < BN) {
        float4 t4 = *reinterpret_cast<const float4*>(&theta_init[i4]);
        *reinterpret_cast<float4*>(&g_theta[i4]) = t4;
        float s0 = sinf(t4.x), s1 = sinf(t4.y), s2 = sinf(t4.z), s3 = sinf(t4.w);
        float c0 = cosf(t4.x), c1 = cosf(t4.y), c2 = cosf(t4.z), c3 = cosf(t4.w);
        float4 sf4 = {s0, s1, s2, s3}, cf4 = {c0, c1, c2, c3};
        *reinterpret_cast<float4*>(&g_sf[i4]) = sf4;
        *reinterpret_cast<float4*>(&g_cf[i4]) = cf4;
        uint32_t sp = (uint32_t)f2e4m3(s0) | ((uint32_t)f2e4m3(s1) << 8)
                    | ((uint32_t)f2e4m3(s2) << 16) | ((uint32_t)f2e4m3(s3) << 24);
        uint32_t cp = (uint32_t)f2e4m3(c0) | ((uint32_t)f2e4m3(c1) << 8)
                    | ((uint32_t)f2e4m3(c2) << 16) | ((uint32_t)f2e4m3(c3) << 24);
        *reinterpret_cast<uint32_t*>(&g_s8[0][i4]) = sp;
        *reinterpret_cast<uint32_t*>(&g_c8[0][i4]) = cp;
    }
}

// ---------------- fused step: fp8 GEMM, 4-way split-K, distributed epilogue ---
__global__ __launch_bounds__(512, 1) void step_kernel(const float* __restrict__ omega,
                                                      const float* __restrict__ kg,
                                                      int rb) {
    extern __shared__ uint8_t sm[];
    const uint32_t sb = s2u(sm);

    const int tid  = threadIdx.x;
    const int lane = tid & 31;
    const int wid  = tid >> 5;          // 0..15
    const int qid  = wid >> 2;          // quarter 0..3 (4 warps each)
    const int qtid = tid & 127;
    const int qwid = wid & 3;
    const int n0   = blockIdx.x * TN;
    const int m0   = blockIdx.y * TM;
    const int wy   = qwid & 1;
    const int wn   = qwid >> 1;
    const int wbuf = rb ^ 1;

    const uint8_t* sin_r = g_s8[rb];
    const uint8_t* cos_r = g_c8[rb];

    // ---- every quarter prefetches ITS OWN quadrant's epilogue state ----------
    const int g = lane >> 2, tig = lane & 3;
    const int half_o = qid & 1, ns_o = qid >> 1;
    const int m_o   = m0 + wy * 16 + half_o * 8 + g;
    const int osc_o = n0 + wn * 16 + ns_o * 8 + tig * 2;
    const int idx_o = m_o * NOSC + osc_o;
    const float om0v = omega[osc_o], om1v = omega[osc_o + 1];
    const float th0 = g_theta[idx_o],     th1 = g_theta[idx_o + 1];
    const float sf0 = g_sf[idx_o],        sf1 = g_sf[idx_o + 1];
    const float cf0 = g_cf[idx_o],        cf1 = g_cf[idx_o + 1];

    // ---- each quarter loads ITS OWN 2 chunks (k = 256 fp8 per quarter) -------
    {
        const int seg = qtid & 7;                  // 16B segment (16 fp8)
        const int r0w = qtid >> 3;                 // 0..15
        const int c0 = qid * QCH;
#pragma unroll
        for (int c = 0; c < QCH; c++) {
            const uint32_t cb = sb + (c0 + c) * CHUNK_B;
            const int kofs = (c0 + c) * 128 + seg * 16;
#pragma unroll
            for (int v = 0; v < 2; v++) {
                const int row = r0w + v * 16;
                const uint32_t doff = (uint32_t)(row * 128 + ((seg ^ (row & 7)) << 4));
                cp16(cb + doff,              sin_r + (size_t)(m0 + row) * NOSC + kofs);
                cp16(cb + TILE_B + doff,     cos_r + (size_t)(m0 + row) * NOSC + kofs);
                cp16(cb + 2 * TILE_B + doff, g_K8  + (size_t)(n0 + row) * NOSC + kofs);
            }
            asm volatile("cp.async.commit_group;" ::: "memory");
        }
    }

    // ---- fragment addressing (byte-identical to bf16-k16 layout) -------------
    const int ar  = wy * 16 + ((lane >> 3) & 1) * 8 + (lane & 7);
    const int asg = lane >> 4;
    const uint32_t a_row = (uint32_t)(ar * 128);
    const int ax  = ar & 7;
    const int brw = wn * 16 + ((lane >> 4) & 1) * 8 + (lane & 7);
    const int bsg = (lane >> 3) & 1;
    const uint32_t b_row = (uint32_t)(brw * 128);
    const int bx  = brw & 7;

    float aS[2][4] = {}, aC[2][4] = {};
    const uint32_t qbase = sb + qid * QCH * CHUNK_B;
    const int barid = qid + 1;

#define DO_CHUNK(c)                                                              \
    asm volatile("cp.async.wait_group %0;" :: "n"(QCH - 1 - (c)) : "memory");    \
    asm volatile("bar.sync %0, 128;" :: "r"(barid) : "memory");                  \
    {                                                                            \
        const uint32_t cb = qbase + (c) * CHUNK_B;                               \
        _Pragma("unroll")                                                        \
        for (int kk = 0; kk < 4; kk++) {      /* k32 fp8 = 32B per kk */         \
            uint32_t aA = cb + a_row + (uint32_t)(((kk * 2 + asg) ^ ax) << 4);   \
            uint32_t aB = cb + 2 * TILE_B + b_row                                \
                        + (uint32_t)(((kk * 2 + bsg) ^ bx) << 4);                \
            uint32_t sa[4], ca[4], bb[4];                                        \
            ldsm4(sa[0], sa[1], sa[2], sa[3], aA);                               \
            ldsm4(ca[0], ca[1], ca[2], ca[3], aA + TILE_B);                      \
            ldsm4(bb[0], bb[1], bb[2], bb[3], aB);                               \
            mma_fp8(aS[0], sa, bb[0], bb[1]);                                    \
            mma_fp8(aS[1], sa, bb[2], bb[3]);                                    \
            mma_fp8(aC[0], ca, bb[0], bb[1]);                                    \
            mma_fp8(aC[1], ca, bb[2], bb[3]);                                    \
        }                                                                        \
    }

    DO_CHUNK(0) DO_CHUNK(1)
#undef DO_CHUNK

    // ---- all-quarter exchange: each stores 16 vals, sums its owned 4 ---------
    __syncthreads();
    float* part = (float*)sm;                 // 32KB overlay (chunks 0-2, done)
    {
        float* pq = part + qid * 2048;        // [16][128] per quarter
#pragma unroll
        for (int ns = 0; ns < 2; ns++)
#pragma unroll
            for (int i = 0; i < 4; i++) {
                pq[(ns * 4 + i) * 128 + qtid]     = aS[ns][i];
                pq[(8 + ns * 4 + i) * 128 + qtid] = aC[ns][i];
            }
    }
    __syncthreads();

    float S0 = aS[ns_o][half_o * 2 + 0], S1 = aS[ns_o][half_o * 2 + 1];
    float C0 = aC[ns_o][half_o * 2 + 0], C1 = aC[ns_o][half_o * 2 + 1];
#pragma unroll
    for (int dq = 1; dq < 4; dq++) {
        float* pq = part + ((qid + dq) & 3) * 2048;
        S0 += pq[(ns_o * 4 + half_o * 2 + 0) * 128 + qtid];
        S1 += pq[(ns_o * 4 + half_o * 2 + 1) * 128 + qtid];
        C0 += pq[(8 + ns_o * 4 + half_o * 2 + 0) * 128 + qtid];
        C1 += pq[(8 + ns_o * 4 + half_o * 2 + 1) * 128 + qtid];
    }

    // ---- epilogue: 2 outputs per thread, fp32 state, fp8 publish -------------
    const float scale = kg[0] * (1.0f / NOSC);
    float t20 = th0 + DT * (om0v + scale * (cf0 * S0 - sf0 * C0));
    float t21 = th1 + DT * (om1v + scale * (cf1 * S1 - sf1 * C1));
    float sn0, cn0, sn1, cn1;
    __sincosf(t20, &sn0, &cn0);
    __sincosf(t21, &sn1, &cn1);
    g_theta[idx_o]     = t20;              // unwrapped; wrap is 2*pi-invariant
    g_theta[idx_o + 1] = t21;
    g_sf[idx_o] = sn0;  g_sf[idx_o + 1] = sn1;
    g_cf[idx_o] = cn0;  g_cf[idx_o + 1] = cn1;
    *reinterpret_cast<unsigned short*>(&g_s8[wbuf][idx_o]) =
        (unsigned short)(f2e4m3(sn0) | ((unsigned short)f2e4m3(sn1) << 8));
    *reinterpret_cast<unsigned short*>(&g_c8[wbuf][idx_o]) =
        (unsigned short)(f2e4m3(cn0) | ((unsigned short)f2e4m3(cn1) << 8));
}

// ---------------- finalize: wrap + coherence (accurate fp32) ------------------
__global__ void finalize_kernel(float* __restrict__ out) {
    __shared__ float rs[256], rc[256];
    const int b = blockIdx.x, tid = threadIdx.x;
    float ss = 0.f, cs = 0.f;
    for (int j = tid; j < NOSC; j += 256) {
        int idx = b * NOSC + j;
        float t = g_theta[idx];
        float sn = sinf(t), cn = cosf(t);
        out[idx] = atan2f(sn, cn);        // wrap to (-pi, pi], matches reference
        ss += sn; cs += cn;
    }
    rs[tid] = ss; rc[tid] = cs;
    __syncthreads();
    for (int off = 128; off > 0; off >>= 1) {
        if (tid < off) { rs[tid] += rs[tid + off]; rc[tid] += rc[tid + off]; }
        __syncthreads();
    }
    if (tid == 0) {
        float sm2 = rs[0] * (1.0f / NOSC);
        float cm  = rc[0] * (1.0f / NOSC);
        out[BN + b] = sqrtf(cm * cm + sm2 * sm2);
    }
}

extern "C" void kernel_launch(void* const* d_in, const int* in_sizes, int n_in,
                              void* d_out, int out_size) {
    const float* theta_init = (const float*)d_in[0];
    const float* K          = (const float*)d_in[1];
    const float* omega      = (const float*)d_in[2];
    const float* kglobal    = (const float*)d_in[3];
    float* out = (float*)d_out;

    cudaFuncSetAttribute(step_kernel, cudaFuncAttributeMaxDynamicSharedMemorySize,
                         SMEM_BYTES);

    init_kernel<<<(NOSC * NOSC) / 1024, 256>>>(theta_init, K);
    dim3 grid(NOSC / TN, BATCH / TM);     // (32, 4) = 128 CTAs
    for (int s = 0; s < STEPS; s++)
        step_kernel<<<grid, 512, SMEM_BYTES>>>(omega, kglobal, s & 1);
    finalize_kernel<<<BATCH, 256>>>(out);
}

// round 13
// speedup vs baseline: 1.0753x; 1.0753x over previous
#include <cuda_runtime.h>
#include <cuda_bf16.h>
#include <math.h>
#include <stdint.h>

#define BATCH 128
#define NOSC  1024
#define STEPS 10
#define DT    0.1f
#define BN    (BATCH*NOSC)

#define TM 32
#define TN 32
#define NCHUNK 16             // k-chunks of 64 bf16
#define QCH 4                 // chunks per quarter
#define TILE_B 4096           // 32 rows x 128B, XOR-swizzled
#define CHUNK_B (3*TILE_B)
#define SMEM_BYTES (NCHUNK*CHUNK_B)   // 196608 B

// ---------------- persistent device state (no allocation allowed) -------------
__device__ float          g_theta[BN];
__device__ __nv_bfloat16  g_sinb[2][BN];
__device__ __nv_bfloat16  g_cosb[2][BN];
__device__ __nv_bfloat16  g_Kb[NOSC*NOSC];

// ---------------- helpers -----------------------------------------------------
__device__ __forceinline__ uint32_t s2u(const void* p) {
    return (uint32_t)__cvta_generic_to_shared(p);
}
__device__ __forceinline__ void cp16(uint32_t dst, const void* src) {
    asm volatile("cp.async.cg.shared.global [%0], [%1], 16;"
                 :: "r"(dst), "l"(src) : "memory");
}
__device__ __forceinline__ void ldsm4(uint32_t& r0, uint32_t& r1, uint32_t& r2,
                                      uint32_t& r3, uint32_t a) {
    asm volatile("ldmatrix.sync.aligned.m8n8.x4.shared.b16 {%0,%1,%2,%3}, [%4];"
                 : "=r"(r0), "=r"(r1), "=r"(r2), "=r"(r3) : "r"(a));
}
__device__ __forceinline__ void mma16816(float* d, const uint32_t* a,
                                         uint32_t b0, uint32_t b1) {
    asm volatile(
        "mma.sync.aligned.m16n8k16.row.col.f32.bf16.bf16.f32 "
        "{%0,%1,%2,%3}, {%4,%5,%6,%7}, {%8,%9}, {%0,%1,%2,%3};"
        : "+f"(d[0]), "+f"(d[1]), "+f"(d[2]), "+f"(d[3])
        : "r"(a[0]), "r"(a[1]), "r"(a[2]), "r"(a[3]), "r"(b0), "r"(b1));
}

// ---------------- init (vectorized) -------------------------------------------
__global__ void init_kernel(const float* __restrict__ theta_init,
                            const float* __restrict__ K) {
    int i4 = (blockIdx.x * blockDim.x + threadIdx.x) * 4;
    float4 k4 = *reinterpret_cast<const float4*>(&K[i4]);
    *reinterpret_cast<__nv_bfloat162*>(&g_Kb[i4])     = __floats2bfloat162_rn(k4.x, k4.y);
    *reinterpret_cast<__nv_bfloat162*>(&g_Kb[i4 + 2]) = __floats2bfloat162_rn(k4.z, k4.w);
    if (i4 < BN) {
        float4 t4 = *reinterpret_cast<const float4*>(&theta_init[i4]);
        *reinterpret_cast<float4*>(&g_theta[i4]) = t4;
        float s0 = sinf(t4.x), s1 = sinf(t4.y), s2 = sinf(t4.z), s3 = sinf(t4.w);
        float c0 = cosf(t4.x), c1 = cosf(t4.y), c2 = cosf(t4.z), c3 = cosf(t4.w);
        *reinterpret_cast<__nv_bfloat162*>(&g_sinb[0][i4])     = __floats2bfloat162_rn(s0, s1);
        *reinterpret_cast<__nv_bfloat162*>(&g_sinb[0][i4 + 2]) = __floats2bfloat162_rn(s2, s3);
        *reinterpret_cast<__nv_bfloat162*>(&g_cosb[0][i4])     = __floats2bfloat162_rn(c0, c1);
        *reinterpret_cast<__nv_bfloat162*>(&g_cosb[0][i4 + 2]) = __floats2bfloat162_rn(c2, c3);
    }
}

// ---------------- fused step: bf16 GEMM, 4-way split-K, PDL overlap -----------
__global__ __launch_bounds__(512, 1) void step_kernel(const float* __restrict__ omega,
                                                      const float* __restrict__ kg,
                                                      int rb) {
    extern __shared__ __nv_bfloat16 sm[];
    const uint32_t sb = s2u(sm);

    const int tid  = threadIdx.x;
    const int lane = tid & 31;
    const int wid  = tid >> 5;          // 0..15
    const int qid  = wid >> 2;          // quarter 0..3 (4 warps each)
    const int qtid = tid & 127;
    const int qwid = wid & 3;
    const int n0   = blockIdx.x * TN;
    const int m0   = blockIdx.y * TM;
    const int wy   = qwid & 1;
    const int wn   = qwid >> 1;
    const int wbuf = rb ^ 1;

    const __nv_bfloat16* sin_r = g_sinb[rb];
    const __nv_bfloat16* cos_r = g_cosb[rb];

    const int seg = qtid & 7;
    const int r0w = qtid >> 3;                 // 0..15
    const int c0  = qid * QCH;

    // ---- phase 1 (no dependency on previous step): K-panel loads -------------
#pragma unroll
    for (int c = 0; c < QCH; c++) {
        const uint32_t cb = sb + (c0 + c) * CHUNK_B;
        const int kofs = (c0 + c) * 64 + seg * 8;
#pragma unroll
        for (int v = 0; v < 2; v++) {
            const int row = r0w + v * 16;
            const uint32_t doff = (uint32_t)(row * 128 + ((seg ^ (row & 7)) << 4));
            cp16(cb + 2 * TILE_B + doff, g_Kb + (size_t)(n0 + row) * NOSC + kofs);
        }
        asm volatile("cp.async.commit_group;" ::: "memory");   // groups K0..K3
    }

    // ---- wait for previous step's grid (PDL; no-op on normal launches) -------
    asm volatile("griddepcontrol.wait;" ::: "memory");

    // ---- phase 2: sin/cos panel loads (depend on previous step) --------------
#pragma unroll
    for (int c = 0; c < QCH; c++) {
        const uint32_t cb = sb + (c0 + c) * CHUNK_B;
        const int kofs = (c0 + c) * 64 + seg * 8;
#pragma unroll
        for (int v = 0; v < 2; v++) {
            const int row = r0w + v * 16;
            const uint32_t doff = (uint32_t)(row * 128 + ((seg ^ (row & 7)) << 4));
            cp16(cb + doff,          sin_r + (size_t)(m0 + row) * NOSC + kofs);
            cp16(cb + TILE_B + doff, cos_r + (size_t)(m0 + row) * NOSC + kofs);
        }
        asm volatile("cp.async.commit_group;" ::: "memory");   // groups S0..S3
    }

    // ---- per-quarter epilogue-state prefetch (own quadrant) ------------------
    const int g = lane >> 2, tig = lane & 3;
    const int half_o = qid & 1, ns_o = qid >> 1;
    const int m_o   = m0 + wy * 16 + half_o * 8 + g;
    const int osc_o = n0 + wn * 16 + ns_o * 8 + tig * 2;
    const int idx_o = m_o * NOSC + osc_o;
    const float om0v = omega[osc_o], om1v = omega[osc_o + 1];
    const float th0 = g_theta[idx_o], th1 = g_theta[idx_o + 1];
    const float sf0 = __bfloat162float(sin_r[idx_o]);
    const float sf1 = __bfloat162float(sin_r[idx_o + 1]);
    const float cf0 = __bfloat162float(cos_r[idx_o]);
    const float cf1 = __bfloat162float(cos_r[idx_o + 1]);

    // ---- fragment addressing (swizzled) --------------------------------------
    const int ar  = wy * 16 + ((lane >> 3) & 1) * 8 + (lane & 7);
    const int asg = lane >> 4;
    const uint32_t a_row = (uint32_t)(ar * 128);
    const int ax  = ar & 7;
    const int brw = wn * 16 + ((lane >> 4) & 1) * 8 + (lane & 7);
    const int bsg = (lane >> 3) & 1;
    const uint32_t b_row = (uint32_t)(brw * 128);
    const int bx  = brw & 7;

    float aS[2][4] = {}, aC[2][4] = {};
    const uint32_t qbase = sb + qid * QCH * CHUNK_B;
    const int barid = qid + 1;

    // chunk c consumable at wait_group(3-c): groups complete in order
    // K0..K3,S0..S3; pending<=3-c implies S_c (and all K) done.
#define DO_CHUNK(c)                                                              \
    asm volatile("cp.async.wait_group %0;" :: "n"(QCH - 1 - (c)) : "memory");    \
    asm volatile("bar.sync %0, 128;" :: "r"(barid) : "memory");                  \
    {                                                                            \
        const uint32_t cb = qbase + (c) * CHUNK_B;                               \
        _Pragma("unroll")                                                        \
        for (int kk = 0; kk < 4; kk++) {                                         \
            uint32_t aA = cb + a_row + (uint32_t)(((kk * 2 + asg) ^ ax) << 4);   \
            uint32_t aB = cb + 2 * TILE_B + b_row                                \
                        + (uint32_t)(((kk * 2 + bsg) ^ bx) << 4);                \
            uint32_t sa[4], ca[4], bb[4];                                        \
            ldsm4(sa[0], sa[1], sa[2], sa[3], aA);                               \
            ldsm4(ca[0], ca[1], ca[2], ca[3], aA + TILE_B);                      \
            ldsm4(bb[0], bb[1], bb[2], bb[3], aB);                               \
            mma16816(aS[0], sa, bb[0], bb[1]);                                   \
            mma16816(aS[1], sa, bb[2], bb[3]);                                   \
            mma16816(aC[0], ca, bb[0], bb[1]);                                   \
            mma16816(aC[1], ca, bb[2], bb[3]);                                   \
        }                                                                        \
    }

    DO_CHUNK(0) DO_CHUNK(1) DO_CHUNK(2) DO_CHUNK(3)
#undef DO_CHUNK

    // ---- all-quarter exchange: each stores 16 partials, sums its owned 4 -----
    __syncthreads();
    float* part = (float*)sm;                 // 32KB overlay (chunks 0-2, done)
    {
        float* pq = part + qid * 2048;        // [16][128] per quarter
#pragma unroll
        for (int ns = 0; ns < 2; ns++)
#pragma unroll
            for (int i = 0; i < 4; i++) {
                pq[(ns * 4 + i) * 128 + qtid]     = aS[ns][i];
                pq[(8 + ns * 4 + i) * 128 + qtid] = aC[ns][i];
            }
    }
    __syncthreads();

    float S0 = aS[ns_o][half_o * 2 + 0], S1 = aS[ns_o][half_o * 2 + 1];
    float C0 = aC[ns_o][half_o * 2 + 0], C1 = aC[ns_o][half_o * 2 + 1];
#pragma unroll
    for (int dq = 1; dq < 4; dq++) {
        float* pq = part + ((qid + dq) & 3) * 2048;
        S0 += pq[(ns_o * 4 + half_o * 2 + 0) * 128 + qtid];
        S1 += pq[(ns_o * 4 + half_o * 2 + 1) * 128 + qtid];
        C0 += pq[(8 + ns_o * 4 + half_o * 2 + 0) * 128 + qtid];
        C1 += pq[(8 + ns_o * 4 + half_o * 2 + 1) * 128 + qtid];
    }

    // ---- epilogue: 2 outputs per thread --------------------------------------
    const float scale = kg[0] * (1.0f / NOSC);
    float t20 = th0 + DT * (om0v + scale * (cf0 * S0 - sf0 * C0));
    float t21 = th1 + DT * (om1v + scale * (cf1 * S1 - sf1 * C1));
    float sn0, cn0, sn1, cn1;
    __sincosf(t20, &sn0, &cn0);
    __sincosf(t21, &sn1, &cn1);
    g_theta[idx_o]     = t20;              // unwrapped; wrap is 2*pi-invariant
    g_theta[idx_o + 1] = t21;
    *reinterpret_cast<__nv_bfloat162*>(&g_sinb[wbuf][idx_o]) =
        __floats2bfloat162_rn(sn0, sn1);
    *reinterpret_cast<__nv_bfloat162*>(&g_cosb[wbuf][idx_o]) =
        __floats2bfloat162_rn(cn0, cn1);
}

// ---------------- finalize: wrap + coherence (accurate fp32) ------------------
__global__ void finalize_kernel(float* __restrict__ out) {
    __shared__ float rs[256], rc[256];
    const int b = blockIdx.x, tid = threadIdx.x;
    float ss = 0.f, cs = 0.f;
    for (int j = tid; j < NOSC; j += 256) {
        int idx = b * NOSC + j;
        float t = g_theta[idx];
        float sn = sinf(t), cn = cosf(t);
        out[idx] = atan2f(sn, cn);        // wrap to (-pi, pi], matches reference
        ss += sn; cs += cn;
    }
    rs[tid] = ss; rc[tid] = cs;
    __syncthreads();
    for (int off = 128; off > 0; off >>= 1) {
        if (tid < off) { rs[tid] += rs[tid + off]; rc[tid] += rc[tid + off]; }
        __syncthreads();
    }
    if (tid == 0) {
        float sm2 = rs[0] * (1.0f / NOSC);
        float cm  = rc[0] * (1.0f / NOSC);
        out[BN + b] = sqrtf(cm * cm + sm2 * sm2);
    }
}

extern "C" void kernel_launch(void* const* d_in, const int* in_sizes, int n_in,
                              void* d_out, int out_size) {
    const float* theta_init = (const float*)d_in[0];
    const float* K          = (const float*)d_in[1];
    const float* omega      = (const float*)d_in[2];
    const float* kglobal    = (const float*)d_in[3];
    float* out = (float*)d_out;

    cudaFuncSetAttribute(step_kernel, cudaFuncAttributeMaxDynamicSharedMemorySize,
                         SMEM_BYTES);

    init_kernel<<<(NOSC * NOSC) / 1024, 256>>>(theta_init, K);

    cudaLaunchConfig_t cfg = {};
    cfg.gridDim  = dim3(NOSC / TN, BATCH / TM, 1);   // (32, 4) = 128 CTAs
    cfg.blockDim = dim3(512, 1, 1);
    cfg.dynamicSmemBytes = SMEM_BYTES;
    cfg.stream = 0;
    cudaLaunchAttribute at[1];
    at[0].id = cudaLaunchAttributeProgrammaticStreamSerialization;
    at[0].val.programmaticStreamSerializationAllowed = 1;

    for (int s = 0; s < STEPS; s++) {
        // step 0 must fully wait for init_kernel (it reads g_Kb pre-wait)
        cfg.attrs    = (s > 0) ? at : nullptr;
        cfg.numAttrs = (s > 0) ? 1 : 0;
        cudaLaunchKernelEx(&cfg, step_kernel, omega, kglobal, s & 1);
    }
    finalize_kernel<<<BATCH, 256>>>(out);
}

// round 14
// speedup vs baseline: 1.1097x; 1.0320x over previous
#include <cuda_runtime.h>
#include <cuda_bf16.h>
#include <math.h>
#include <stdint.h>

#define BATCH 128
#define NOSC  1024
#define STEPS 10
#define DT    0.1f
#define BN    (BATCH*NOSC)

#define TM 32
#define TN 32
#define NCHUNK 16             // k-chunks of 64 bf16
#define QCH 4                 // chunks per quarter
#define TILE_B 4096           // 32 rows x 128B, XOR-swizzled
#define CHUNK_B (3*TILE_B)
#define SMEM_BYTES (NCHUNK*CHUNK_B)   // 196608 B

// ---------------- persistent device state (no allocation allowed) -------------
__device__ float          g_theta[BN];
__device__ __nv_bfloat16  g_sinb[2][BN];
__device__ __nv_bfloat16  g_cosb[2][BN];
__device__ __nv_bfloat16  g_Kb[NOSC*NOSC];

// ---------------- helpers -----------------------------------------------------
__device__ __forceinline__ uint32_t s2u(const void* p) {
    return (uint32_t)__cvta_generic_to_shared(p);
}
__device__ __forceinline__ void cp16(uint32_t dst, const void* src) {
    asm volatile("cp.async.cg.shared.global [%0], [%1], 16;"
                 :: "r"(dst), "l"(src) : "memory");
}
__device__ __forceinline__ void ldsm4(uint32_t& r0, uint32_t& r1, uint32_t& r2,
                                      uint32_t& r3, uint32_t a) {
    asm volatile("ldmatrix.sync.aligned.m8n8.x4.shared.b16 {%0,%1,%2,%3}, [%4];"
                 : "=r"(r0), "=r"(r1), "=r"(r2), "=r"(r3) : "r"(a));
}
__device__ __forceinline__ void mma16816(float* d, const uint32_t* a,
                                         uint32_t b0, uint32_t b1) {
    asm volatile(
        "mma.sync.aligned.m16n8k16.row.col.f32.bf16.bf16.f32 "
        "{%0,%1,%2,%3}, {%4,%5,%6,%7}, {%8,%9}, {%0,%1,%2,%3};"
        : "+f"(d[0]), "+f"(d[1]), "+f"(d[2]), "+f"(d[3])
        : "r"(a[0]), "r"(a[1]), "r"(a[2]), "r"(a[3]), "r"(b0), "r"(b1));
}
__device__ __forceinline__ void pdl_wait() {
    asm volatile("griddepcontrol.wait;" ::: "memory");
}
__device__ __forceinline__ void pdl_trigger() {
    asm volatile("griddepcontrol.launch_dependents;" ::: "memory");
}

// ---------------- init: 8 elems/thread (2x MLP) -------------------------------
__global__ void init_kernel(const float* __restrict__ theta_init,
                            const float* __restrict__ K) {
    int i8 = (blockIdx.x * blockDim.x + threadIdx.x) * 8;
#pragma unroll
    for (int h = 0; h < 2; h++) {
        int i4 = i8 + h * 4;
        float4 k4 = *reinterpret_cast<const float4*>(&K[i4]);
        *reinterpret_cast<__nv_bfloat162*>(&g_Kb[i4])     = __floats2bfloat162_rn(k4.x, k4.y);
        *reinterpret_cast<__nv_bfloat162*>(&g_Kb[i4 + 2]) = __floats2bfloat162_rn(k4.z, k4.w);
        if (i4 < BN) {
            float4 t4 = *reinterpret_cast<const float4*>(&theta_init[i4]);
            *reinterpret_cast<float4*>(&g_theta[i4]) = t4;
            float s0 = sinf(t4.x), s1 = sinf(t4.y), s2 = sinf(t4.z), s3 = sinf(t4.w);
            float c0 = cosf(t4.x), c1 = cosf(t4.y), c2 = cosf(t4.z), c3 = cosf(t4.w);
            *reinterpret_cast<__nv_bfloat162*>(&g_sinb[0][i4])     = __floats2bfloat162_rn(s0, s1);
            *reinterpret_cast<__nv_bfloat162*>(&g_sinb[0][i4 + 2]) = __floats2bfloat162_rn(s2, s3);
            *reinterpret_cast<__nv_bfloat162*>(&g_cosb[0][i4])     = __floats2bfloat162_rn(c0, c1);
            *reinterpret_cast<__nv_bfloat162*>(&g_cosb[0][i4 + 2]) = __floats2bfloat162_rn(c2, c3);
        }
    }
}

// ---------------- fused step: bf16 GEMM, 4-way split-K, PDL both ways ---------
__global__ __launch_bounds__(512, 1) void step_kernel(const float* __restrict__ omega,
                                                      const float* __restrict__ kg,
                                                      int rb, int early) {
    extern __shared__ __nv_bfloat16 sm[];
    const uint32_t sb = s2u(sm);

    const int tid  = threadIdx.x;
    const int lane = tid & 31;
    const int wid  = tid >> 5;          // 0..15
    const int qid  = wid >> 2;          // quarter 0..3 (4 warps each)
    const int qtid = tid & 127;
    const int qwid = wid & 3;
    const int n0   = blockIdx.x * TN;
    const int m0   = blockIdx.y * TM;
    const int wy   = qwid & 1;
    const int wn   = qwid >> 1;
    const int wbuf = rb ^ 1;

    const __nv_bfloat16* sin_r = g_sinb[rb];
    const __nv_bfloat16* cos_r = g_cosb[rb];

    const int seg = qtid & 7;
    const int r0w = qtid >> 3;                 // 0..15
    const int c0  = qid * QCH;

    // step 0: K depends on init_kernel -> wait BEFORE K loads
    if (!early) pdl_wait();

    // ---- phase 1: K-panel loads (const across steps when early) --------------
#pragma unroll
    for (int c = 0; c < QCH; c++) {
        const uint32_t cb = sb + (c0 + c) * CHUNK_B;
        const int kofs = (c0 + c) * 64 + seg * 8;
#pragma unroll
        for (int v = 0; v < 2; v++) {
            const int row = r0w + v * 16;
            const uint32_t doff = (uint32_t)(row * 128 + ((seg ^ (row & 7)) << 4));
            cp16(cb + 2 * TILE_B + doff, g_Kb + (size_t)(n0 + row) * NOSC + kofs);
        }
        asm volatile("cp.async.commit_group;" ::: "memory");   // groups K0..K3
    }

    // steps 1..9: wait for previous step before touching sin/cos
    if (early) pdl_wait();

    // ---- phase 2: sin/cos panel loads ----------------------------------------
#pragma unroll
    for (int c = 0; c < QCH; c++) {
        const uint32_t cb = sb + (c0 + c) * CHUNK_B;
        const int kofs = (c0 + c) * 64 + seg * 8;
#pragma unroll
        for (int v = 0; v < 2; v++) {
            const int row = r0w + v * 16;
            const uint32_t doff = (uint32_t)(row * 128 + ((seg ^ (row & 7)) << 4));
            cp16(cb + doff,          sin_r + (size_t)(m0 + row) * NOSC + kofs);
            cp16(cb + TILE_B + doff, cos_r + (size_t)(m0 + row) * NOSC + kofs);
        }
        asm volatile("cp.async.commit_group;" ::: "memory");   // groups S0..S3
    }

    // ---- per-quarter epilogue-state prefetch (own quadrant) ------------------
    const int g = lane >> 2, tig = lane & 3;
    const int half_o = qid & 1, ns_o = qid >> 1;
    const int m_o   = m0 + wy * 16 + half_o * 8 + g;
    const int osc_o = n0 + wn * 16 + ns_o * 8 + tig * 2;
    const int idx_o = m_o * NOSC + osc_o;
    const float om0v = omega[osc_o], om1v = omega[osc_o + 1];
    const float th0 = g_theta[idx_o], th1 = g_theta[idx_o + 1];
    const float sf0 = __bfloat162float(sin_r[idx_o]);
    const float sf1 = __bfloat162float(sin_r[idx_o + 1]);
    const float cf0 = __bfloat162float(cos_r[idx_o]);
    const float cf1 = __bfloat162float(cos_r[idx_o + 1]);

    // ---- fragment addressing (swizzled) --------------------------------------
    const int ar  = wy * 16 + ((lane >> 3) & 1) * 8 + (lane & 7);
    const int asg = lane >> 4;
    const uint32_t a_row = (uint32_t)(ar * 128);
    const int ax  = ar & 7;
    const int brw = wn * 16 + ((lane >> 4) & 1) * 8 + (lane & 7);
    const int bsg = (lane >> 3) & 1;
    const uint32_t b_row = (uint32_t)(brw * 128);
    const int bx  = brw & 7;

    float aS[2][4] = {}, aC[2][4] = {};
    const uint32_t qbase = sb + qid * QCH * CHUNK_B;
    const int barid = qid + 1;

#define DO_CHUNK(c)                                                              \
    asm volatile("cp.async.wait_group %0;" :: "n"(QCH - 1 - (c)) : "memory");    \
    asm volatile("bar.sync %0, 128;" :: "r"(barid) : "memory");                  \
    {                                                                            \
        const uint32_t cb = qbase + (c) * CHUNK_B;                               \
        _Pragma("unroll")                                                        \
        for (int kk = 0; kk < 4; kk++) {                                         \
            uint32_t aA = cb + a_row + (uint32_t)(((kk * 2 + asg) ^ ax) << 4);   \
            uint32_t aB = cb + 2 * TILE_B + b_row                                \
                        + (uint32_t)(((kk * 2 + bsg) ^ bx) << 4);                \
            uint32_t sa[4], ca[4], bb[4];                                        \
            ldsm4(sa[0], sa[1], sa[2], sa[3], aA);                               \
            ldsm4(ca[0], ca[1], ca[2], ca[3], aA + TILE_B);                      \
            ldsm4(bb[0], bb[1], bb[2], bb[3], aB);                               \
            mma16816(aS[0], sa, bb[0], bb[1]);                                   \
            mma16816(aS[1], sa, bb[2], bb[3]);                                   \
            mma16816(aC[0], ca, bb[0], bb[1]);                                   \
            mma16816(aC[1], ca, bb[2], bb[3]);                                   \
        }                                                                        \
    }

    DO_CHUNK(0) DO_CHUNK(1) DO_CHUNK(2) DO_CHUNK(3)
#undef DO_CHUNK

    // ---- GEMM done: let the next step's CTAs launch & prefetch K NOW ---------
    pdl_trigger();

    // ---- all-quarter exchange: each stores 16 partials, sums its owned 4 -----
    __syncthreads();
    float* part = (float*)sm;                 // 32KB overlay (chunks 0-2, done)
    {
        float* pq = part + qid * 2048;        // [16][128] per quarter
#pragma unroll
        for (int ns = 0; ns < 2; ns++)
#pragma unroll
            for (int i = 0; i < 4; i++) {
                pq[(ns * 4 + i) * 128 + qtid]     = aS[ns][i];
                pq[(8 + ns * 4 + i) * 128 + qtid] = aC[ns][i];
            }
    }
    __syncthreads();

    float S0 = aS[ns_o][half_o * 2 + 0], S1 = aS[ns_o][half_o * 2 + 1];
    float C0 = aC[ns_o][half_o * 2 + 0], C1 = aC[ns_o][half_o * 2 + 1];
#pragma unroll
    for (int dq = 1; dq < 4; dq++) {
        float* pq = part + ((qid + dq) & 3) * 2048;
        S0 += pq[(ns_o * 4 + half_o * 2 + 0) * 128 + qtid];
        S1 += pq[(ns_o * 4 + half_o * 2 + 1) * 128 + qtid];
        C0 += pq[(8 + ns_o * 4 + half_o * 2 + 0) * 128 + qtid];
        C1 += pq[(8 + ns_o * 4 + half_o * 2 + 1) * 128 + qtid];
    }

    // ---- epilogue: 2 outputs per thread --------------------------------------
    const float scale = kg[0] * (1.0f / NOSC);
    float t20 = th0 + DT * (om0v + scale * (cf0 * S0 - sf0 * C0));
    float t21 = th1 + DT * (om1v + scale * (cf1 * S1 - sf1 * C1));
    float sn0, cn0, sn1, cn1;
    __sincosf(t20, &sn0, &cn0);
    __sincosf(t21, &sn1, &cn1);
    g_theta[idx_o]     = t20;              // unwrapped; wrap is 2*pi-invariant
    g_theta[idx_o + 1] = t21;
    *reinterpret_cast<__nv_bfloat162*>(&g_sinb[wbuf][idx_o]) =
        __floats2bfloat162_rn(sn0, sn1);
    *reinterpret_cast<__nv_bfloat162*>(&g_cosb[wbuf][idx_o]) =
        __floats2bfloat162_rn(cn0, cn1);
}

// ---------------- finalize: PDL + cheap wrap + coherence ----------------------
__global__ void finalize_kernel(float* __restrict__ out) {
    pdl_wait();
    __shared__ float rs[256], rc[256];
    const int b = blockIdx.x, tid = threadIdx.x;
    float ss = 0.f, cs = 0.f;
    for (int j = tid; j < NOSC; j += 256) {
        int idx = b * NOSC + j;
        float t = g_theta[idx];
        float sn, cn;
        __sincosf(t, &sn, &cn);
        // wrap to (-pi, pi]: equals atan2(sin t, cos t) up to ~1e-7
        out[idx] = t - 6.283185307179586f * rintf(t * 0.15915494309189535f);
        ss += sn; cs += cn;
    }
    rs[tid] = ss; rc[tid] = cs;
    __syncthreads();
    for (int off = 128; off > 0; off >>= 1) {
        if (tid < off) { rs[tid] += rs[tid + off]; rc[tid] += rc[tid + off]; }
        __syncthreads();
    }
    if (tid == 0) {
        float sm2 = rs[0] * (1.0f / NOSC);
        float cm  = rc[0] * (1.0f / NOSC);
        out[BN + b] = sqrtf(cm * cm + sm2 * sm2);
    }
}

extern "C" void kernel_launch(void* const* d_in, const int* in_sizes, int n_in,
                              void* d_out, int out_size) {
    const float* theta_init = (const float*)d_in[0];
    const float* K          = (const float*)d_in[1];
    const float* omega      = (const float*)d_in[2];
    const float* kglobal    = (const float*)d_in[3];
    float* out = (float*)d_out;

    cudaFuncSetAttribute(step_kernel, cudaFuncAttributeMaxDynamicSharedMemorySize,
                         SMEM_BYTES);

    init_kernel<<<(NOSC * NOSC) / 2048, 256>>>(theta_init, K);

    cudaLaunchAttribute at[1];
    at[0].id = cudaLaunchAttributeProgrammaticStreamSerialization;
    at[0].val.programmaticStreamSerializationAllowed = 1;

    cudaLaunchConfig_t cfg = {};
    cfg.gridDim  = dim3(NOSC / TN, BATCH / TM, 1);   // (32, 4) = 128 CTAs
    cfg.blockDim = dim3(512, 1, 1);
    cfg.dynamicSmemBytes = SMEM_BYTES;
    cfg.stream = 0;
    cfg.attrs    = at;
    cfg.numAttrs = 1;

    for (int s = 0; s < STEPS; s++)
        cudaLaunchKernelEx(&cfg, step_kernel, omega, kglobal, s & 1, (int)(s > 0));

    cudaLaunchConfig_t fcfg = {};
    fcfg.gridDim  = dim3(BATCH, 1, 1);
    fcfg.blockDim = dim3(256, 1, 1);
    fcfg.stream   = 0;
    fcfg.attrs    = at;
    fcfg.numAttrs = 1;
    cudaLaunchKernelEx(&fcfg, finalize_kernel, out);
}